// round 17
// baseline (speedup 1.0000x reference)
#include <cuda_runtime.h>

#define BB 64
#define CC 512
#define TT 16
#define HWD 196
#define KK 8
#define CPB 2                 // channels per pool block

// [b][t][c] per-channel partial scores
__device__ float g_partial[BB * TT * CC];
// [b][t] -> output slot 0..15 (0-7 = approx pos, 8-15 = 8+detail pos)
__device__ int   g_dest[BB * TT];

// ---------------------------------------------------------------------------
// Kernel 1: pool via registers + butterfly shuffles (smem nearly eliminated).
// Thread p<224 = (ch = p/112, y = (p%112)/16, t = p%16): strip rows 2y,2y+1
// of frame t -> 7 pooled values in registers (7 independent LDG.128).
// sc[blk]: 16-lane xor-butterfly over t (t-groups are 16-aligned in the warp).
// Per-thread 7-FMA partial dot, then tiny smem reduce over y (224 STS/LDS).
// ---------------------------------------------------------------------------
__global__ __launch_bounds__(256) void k_pool(const float* __restrict__ x) {
    __shared__ float sm[CPB * 112];           // 224 floats

    const int bc0 = blockIdx.x * CPB;
    const float* __restrict__ base = x + (size_t)bc0 * (TT * HWD);

    const int p = threadIdx.x;
    if (p < CPB * 112) {                      // warps 0..6 fully active
        const int ch  = p / 112;
        const int rem = p - ch * 112;
        const int y   = rem >> 4;             // pool row (input rows 2y,2y+1)
        const int t   = rem & 15;

        const float4* __restrict__ sp =
            (const float4*)(base + (ch * TT + t) * HWD + y * 28);
        float4 r0 = sp[0], r1 = sp[1], r2 = sp[2], r3 = sp[3];
        float4 r4 = sp[4], r5 = sp[5], r6 = sp[6];

        float pl[7];
        pl[0] = 0.25f * (r0.x + r0.y + r3.z + r3.w);
        pl[1] = 0.25f * (r0.z + r0.w + r4.x + r4.y);
        pl[2] = 0.25f * (r1.x + r1.y + r4.z + r4.w);
        pl[3] = 0.25f * (r1.z + r1.w + r5.x + r5.y);
        pl[4] = 0.25f * (r2.x + r2.y + r5.z + r5.w);
        pl[5] = 0.25f * (r2.z + r2.w + r6.x + r6.y);
        pl[6] = 0.25f * (r3.x + r3.y + r6.z + r6.w);

        // sc_i = sum over the 16 t-lanes of pl[i]; butterfly leaves the sum
        // in every lane. acc = partial dot over this thread's 7 blocks.
        float acc = 0.f;
        #pragma unroll
        for (int i = 0; i < 7; i++) {
            float v = pl[i];
            v += __shfl_xor_sync(0xffffffffu, v, 1);
            v += __shfl_xor_sync(0xffffffffu, v, 2);
            v += __shfl_xor_sync(0xffffffffu, v, 4);
            v += __shfl_xor_sync(0xffffffffu, v, 8);
            acc += pl[i] * v;
        }
        sm[p] = acc;
    }
    __syncthreads();

    if (threadIdx.x < CPB * TT) {             // 32 threads: reduce over y
        const int ch = threadIdx.x >> 4;
        const int t  = threadIdx.x & 15;
        float s = 0.f;
        #pragma unroll
        for (int y = 0; y < 7; y++)
            s += sm[ch * 112 + y * 16 + t];
        const int bc = bc0 + ch;
        g_partial[((bc >> 9) * TT + t) * CC + (bc & (CC - 1))] = s;
    }
}

// ---------------------------------------------------------------------------
// Kernel 2 (proven ~3us): fused channel-reduce + selection, block per b.
// ---------------------------------------------------------------------------
__global__ __launch_bounds__(256) void k_score_select() {
    __shared__ float v[TT];
    __shared__ int fa[TT], fd[TT];
    const int b = blockIdx.x;
    const int t = threadIdx.x >> 4;
    const int g = threadIdx.x & 15;

    const float* __restrict__ p = g_partial + (b * TT + t) * CC;
    float s = 0.f;
    #pragma unroll
    for (int j = 0; j < CC / 16; j++) s += p[g + 16 * j];
    s += __shfl_xor_sync(0xffffffffu, s, 8);
    s += __shfl_xor_sync(0xffffffffu, s, 4);
    s += __shfl_xor_sync(0xffffffffu, s, 2);
    s += __shfl_xor_sync(0xffffffffu, s, 1);
    if (g == 0)
        v[t] = s * (1.0f / (float)(CC * TT)) + ((t & 1) == 0 ? 1.0f : 0.0f);
    __syncthreads();

    if (threadIdx.x < TT) {                   // jax top_k tie semantics
        const int i = threadIdx.x;
        const float mv = v[i];
        int ra = 0, rd = 0;
        #pragma unroll
        for (int j = 0; j < TT; j++) {
            ra += (v[j] > mv) || (v[j] == mv && j < i);
            rd += (v[j] < mv) || (v[j] == mv && j < i);
        }
        fa[i] = (ra < KK);
        fd[i] = (rd < KK);
    }
    __syncthreads();
    if (threadIdx.x < TT) {
        const int i = threadIdx.x;
        int pa = 0, pd = 0;
        for (int j = 0; j < i; j++) { pa += fa[j]; pd += fd[j]; }
        // ranks form a permutation (ra+rd==15): exactly one of fa/fd is set
        g_dest[b * TT + i] = fa[i] ? pa : (KK + pd);
    }
}

// ---------------------------------------------------------------------------
// Kernel 3 (R16, proven): gather with 8 independent float4s per thread,
// regions in DESCENDING order to consume k_pool's L2-resident tail first.
// ---------------------------------------------------------------------------
#define TOTAL4   (BB * CC * TT * (HWD / 4))   // 25,690,112 float4s
#define G_MLP    8
#define G_BLOCKS (TOTAL4 / (G_MLP * 256))     // 12544

__global__ __launch_bounds__(256) void k_gather(const float* __restrict__ x,
                                                float* __restrict__ out) {
    const float4* __restrict__ src4 = (const float4*)x;
    float4* __restrict__ out4 = (float4*)out;

    const unsigned base =
        (unsigned)(G_BLOCKS - 1 - blockIdx.x) * (G_MLP * 256u) + threadIdx.x;

    float4 val[G_MLP];
    #pragma unroll
    for (int k = 0; k < G_MLP; k++)
        val[k] = __ldcs(&src4[base + (unsigned)k * 256u]);   // 8 indep loads

    #pragma unroll
    for (int k = 0; k < G_MLP; k++) {
        unsigned i = base + (unsigned)k * 256u;
        unsigned hw4 = i % 49u;
        unsigned r = i / 49u;
        unsigned t = r & (TT - 1);
        unsigned c = (r >> 4) & (CC - 1);
        unsigned b = r >> 13;
        int s = __ldg(&g_dest[b * TT + t]);
        unsigned half = (unsigned)s >> 3;
        unsigned j = (unsigned)s & (KK - 1);
        unsigned o = half * (BB * CC * KK * 49u)
                   + ((b * CC + c) * KK + j) * 49u + hw4;
        __stcs(&out4[o], val[k]);
    }
}

// ---------------------------------------------------------------------------
extern "C" void kernel_launch(void* const* d_in, const int* in_sizes, int n_in,
                              void* d_out, int out_size) {
    const float* x = (const float*)d_in[0];
    float* out = (float*)d_out;

    k_pool<<<(BB * CC) / CPB, 256>>>(x);
    k_score_select<<<BB, 256>>>();
    k_gather<<<G_BLOCKS, 256>>>(x, out);
}